// round 9
// baseline (speedup 1.0000x reference)
#include <cuda_runtime.h>
#include <cuda_fp16.h>
#include <cstdint>
#include <math.h>

#define B_BATCH 4
#define T_SEQ   4096
#define C_DIM   1024
#define HSZ     128
#define CH      18     // k-iters per split chunk -> 74 chunks x 4 b = 296 CTAs

// Scratch (device globals: no runtime allocation)
__device__ __half g_xh [B_BATCH * T_SEQ * C_DIM];   // x in fp16
__device__ __half g_wth[3 * HSZ * C_DIM];           // [mat][n][k] fp16 (transposed)
__device__ __half g_qh [B_BATCH * T_SEQ * HSZ];     // [b][t][h]
__device__ __half g_kh [B_BATCH * T_SEQ * HSZ];     // [b][t][h]
__device__ __half g_vth[B_BATCH * HSZ * T_SEQ];     // [b][h][t] (transposed)
__device__ float  g_opart[B_BATCH * 32 * 4 * 128 * 128];
__device__ float  g_lpart[B_BATCH * 32 * 4 * 128];

__device__ __forceinline__ float ex2f(float x) {
    float y; asm("ex2.approx.f32 %0, %1;" : "=f"(y) : "f"(x)); return y;
}
__device__ __forceinline__ unsigned h2u(float a, float b) {
    __half2 h = __floats2half2_rn(a, b);
    return *reinterpret_cast<unsigned*>(&h);
}

// D(16x8 f32) += A(16x16 f16) * B(16x8 f16)
__device__ __forceinline__ void mma_f16(
    float& d0, float& d1, float& d2, float& d3,
    unsigned a0, unsigned a1, unsigned a2, unsigned a3,
    unsigned b0, unsigned b1)
{
    asm volatile(
        "mma.sync.aligned.m16n8k16.row.col.f32.f16.f16.f32 "
        "{%0,%1,%2,%3},{%4,%5,%6,%7},{%8,%9},{%0,%1,%2,%3};"
        : "+f"(d0), "+f"(d1), "+f"(d2), "+f"(d3)
        : "r"(a0), "r"(a1), "r"(a2), "r"(a3), "r"(b0), "r"(b1));
}

__device__ __forceinline__ void ldsm4(unsigned& r0, unsigned& r1,
                                      unsigned& r2, unsigned& r3, unsigned addr)
{
    asm volatile("ldmatrix.sync.aligned.m8n8.x4.shared.b16 {%0,%1,%2,%3}, [%4];"
                 : "=r"(r0), "=r"(r1), "=r"(r2), "=r"(r3) : "r"(addr));
}

__device__ __forceinline__ void cp16(void* dst_smem, const void* src) {
    unsigned d = (unsigned)__cvta_generic_to_shared(dst_smem);
    asm volatile("cp.async.cg.shared.global [%0], [%1], 16;" :: "r"(d), "l"(src));
}
#define CP_COMMIT() asm volatile("cp.async.commit_group;" ::: "memory")
#define CP_WAIT1()  asm volatile("cp.async.wait_group 1;" ::: "memory")

// ---------------------------------------------------------------------------
// x -> fp16
// ---------------------------------------------------------------------------
__global__ __launch_bounds__(256) void xh_kernel(const float* __restrict__ x)
{
    const size_t i = ((size_t)blockIdx.x * 256 + threadIdx.x) * 8;
    float4 v0 = *reinterpret_cast<const float4*>(x + i);
    float4 v1 = *reinterpret_cast<const float4*>(x + i + 4);
    uint4 o;
    o.x = h2u(v0.x, v0.y); o.y = h2u(v0.z, v0.w);
    o.z = h2u(v1.x, v1.y); o.w = h2u(v1.z, v1.w);
    *reinterpret_cast<uint4*>(g_xh + i) = o;
}

// ---------------------------------------------------------------------------
// W prep: g_wth[mat][n][k] = fp16(W[k][n])
// ---------------------------------------------------------------------------
__global__ __launch_bounds__(256) void wt_kernel(
    const float* __restrict__ Wq, const float* __restrict__ Wk,
    const float* __restrict__ Wv)
{
    __shared__ float t[32][33];
    const float* __restrict__ W =
        (blockIdx.z == 0) ? Wq : (blockIdx.z == 1 ? Wk : Wv);
    const int k0 = blockIdx.x * 32, n0 = blockIdx.y * 32;
    const int tx = threadIdx.x & 31, ty = threadIdx.x >> 5;
#pragma unroll
    for (int r = ty; r < 32; r += 8)
        t[r][tx] = W[(size_t)(k0 + r) * HSZ + n0 + tx];
    __syncthreads();
    __half* dst = g_wth + (size_t)blockIdx.z * HSZ * C_DIM;
#pragma unroll
    for (int r = ty; r < 32; r += 8)
        dst[(size_t)(n0 + r) * C_DIM + k0 + tx] = __float2half_rn(t[tx][r]);
}

// ---------------------------------------------------------------------------
// Projection fp16 (proven R8): out = x @ W. 256 thr, M=128 N=128, KC=64.
// ---------------------------------------------------------------------------
#define PJS   72
#define PJBUF (128 * PJS)
#define PROJ_SMEM (4 * PJBUF * 2)

__global__ __launch_bounds__(256, 2) void proj_kernel()
{
    extern __shared__ char psm[];
    __half* xs = reinterpret_cast<__half*>(psm);
    __half* ws = xs + 2 * PJBUF;
    const uint32_t smu = (uint32_t)__cvta_generic_to_shared(psm);

    const int mat  = blockIdx.y;
    const int row0 = blockIdx.x * 128;
    const int tid  = threadIdx.x;
    const int lane = tid & 31, wid = tid >> 5;
    const int wm = wid >> 1, wn = wid & 1;
    const int g = lane >> 2, tg = lane & 3;
    const int j = lane & 7, mq = lane >> 3;

    const int lrow = j + ((mq & 1) << 3);
    const int lcol = (mq >> 1) << 3;
    const uint32_t aOff = (uint32_t)(((wm * 32 + lrow) * PJS + lcol) * 2);
    const uint32_t bOff = (uint32_t)(((wn * 64 + lrow) * PJS + lcol) * 2);
    const uint32_t xB0 = smu, xB1 = smu + PJBUF * 2;
    const uint32_t wB0 = smu + 2 * PJBUF * 2, wB1 = smu + 3 * PJBUF * 2;

    const __half* wsrc = g_wth + (size_t)mat * HSZ * C_DIM;
    const __half* xsrc = g_xh + (size_t)row0 * C_DIM;

    auto issue = [&](int kc, int buf) {
#pragma unroll
        for (int u = 0; u < 4; u++) {
            const int i = tid + u * 256;
            const int r = i >> 3, ch = i & 7;
            cp16(xs + buf * PJBUF + r * PJS + ch * 8,
                 xsrc + (size_t)r * C_DIM + kc + ch * 8);
        }
#pragma unroll
        for (int u = 0; u < 4; u++) {
            const int i = tid + u * 256;
            const int r = i >> 3, ch = i & 7;
            cp16(ws + buf * PJBUF + r * PJS + ch * 8,
                 wsrc + (size_t)r * C_DIM + kc + ch * 8);
        }
    };

    float acc[2][8][4];
#pragma unroll
    for (int mi = 0; mi < 2; mi++)
#pragma unroll
        for (int ni = 0; ni < 8; ni++)
#pragma unroll
            for (int q = 0; q < 4; q++) acc[mi][ni][q] = 0.f;

    issue(0, 0);  CP_COMMIT();
    issue(64, 1); CP_COMMIT();

    for (int kci = 0; kci < 16; kci++) {
        CP_WAIT1();
        __syncthreads();
        const uint32_t xB = (kci & 1) ? xB1 : xB0;
        const uint32_t wB = (kci & 1) ? wB1 : wB0;

#pragma unroll
        for (int kf = 0; kf < 4; kf++) {
            unsigned a[2][4];
#pragma unroll
            for (int mi = 0; mi < 2; mi++)
                ldsm4(a[mi][0], a[mi][1], a[mi][2], a[mi][3],
                      xB + aOff + (uint32_t)(mi * 16 * PJS * 2 + kf * 32));
#pragma unroll
            for (int p = 0; p < 4; p++) {
                unsigned r0, r1, r2, r3;
                ldsm4(r0, r1, r2, r3,
                      wB + bOff + (uint32_t)(p * 16 * PJS * 2 + kf * 32));
#pragma unroll
                for (int mi = 0; mi < 2; mi++) {
                    mma_f16(acc[mi][2*p][0], acc[mi][2*p][1],
                            acc[mi][2*p][2], acc[mi][2*p][3],
                            a[mi][0], a[mi][1], a[mi][2], a[mi][3], r0, r2);
                    mma_f16(acc[mi][2*p+1][0], acc[mi][2*p+1][1],
                            acc[mi][2*p+1][2], acc[mi][2*p+1][3],
                            a[mi][0], a[mi][1], a[mi][2], a[mi][3], r1, r3);
                }
            }
        }
        __syncthreads();
        if (kci + 2 < 16) issue((kci + 2) * 64, kci & 1);
        CP_COMMIT();
    }

    if (mat != 2) {
        __half* out = (mat == 0) ? g_qh : g_kh;
#pragma unroll
        for (int mi = 0; mi < 2; mi++)
#pragma unroll
            for (int ni = 0; ni < 8; ni++) {
                const int r = row0 + wm * 32 + mi * 16 + g;
                const int c = wn * 64 + ni * 8 + 2 * tg;
                *reinterpret_cast<__half2*>(out + (size_t)r * HSZ + c) =
                    __floats2half2_rn(acc[mi][ni][0], acc[mi][ni][1]);
                *reinterpret_cast<__half2*>(out + (size_t)(r + 8) * HSZ + c) =
                    __floats2half2_rn(acc[mi][ni][2], acc[mi][ni][3]);
            }
    } else {
        __syncthreads();
        float* st = reinterpret_cast<float*>(psm);
#pragma unroll
        for (int mi = 0; mi < 2; mi++)
#pragma unroll
            for (int ni = 0; ni < 8; ni++) {
                const int rl = wm * 32 + mi * 16 + g;
                const int c  = wn * 64 + ni * 8 + 2 * tg;
                st[rl * 129 + c]           = acc[mi][ni][0];
                st[rl * 129 + c + 1]       = acc[mi][ni][1];
                st[(rl + 8) * 129 + c]     = acc[mi][ni][2];
                st[(rl + 8) * 129 + c + 1] = acc[mi][ni][3];
            }
        __syncthreads();
        const int bb = blockIdx.x >> 5;
        const int tbase = row0 & (T_SEQ - 1);
        const int h = tid >> 1;
        __half* dst = g_vth + ((size_t)(bb * HSZ + h)) * T_SEQ + tbase + (tid & 1) * 64;
#pragma unroll
        for (int v = 0; v < 16; v++) {
            const int t0 = (tid & 1) * 64 + v * 4;
            uint2 o;
            o.x = h2u(st[(t0 + 0) * 129 + h], st[(t0 + 1) * 129 + h]);
            o.y = h2u(st[(t0 + 2) * 129 + h], st[(t0 + 3) * 129 + h]);
            *reinterpret_cast<uint2*>(dst + v * 4) = o;
        }
    }
}

// ---------------------------------------------------------------------------
// Split-K flash attention fp16 v2: per-16-key fused exp+pack+PV pipeline
// (MUFU of chunk kf+1 overlaps HMMA of chunk kf). 256 thr, BM=128, BN=64.
// ---------------------------------------------------------------------------
#define QSH  136
#define KSH  136
#define VSH  72
#define Q_HL (128 * QSH)
#define K_HL (64 * KSH)
#define V_HL (128 * VSH)
#define ATTN_SMEM ((Q_HL + 2 * K_HL + 2 * V_HL) * 2)   // 106,496 B

__global__ __launch_bounds__(256, 2) void attn_kernel()
{
    extern __shared__ char smc[];
    __half* Qsh = reinterpret_cast<__half*>(smc);
    __half* Kb  = Qsh + Q_HL;
    __half* Vb  = Qsh + Q_HL + 2 * K_HL;
    const uint32_t smu = (uint32_t)__cvta_generic_to_shared(smc);

    const int b = blockIdx.y;

    int idx = blockIdx.x, qt = 0, sidx = 0, cs = 0, cl = 0;
    for (int q = 31; q >= 0; q--) {
        const int n = 2 * q + 2, nc = (n + CH - 1) / CH;
        if (idx < nc) { qt = q; sidx = idx; cs = idx * CH; cl = min(CH, n - cs); break; }
        idx -= nc;
    }
    const int row0 = qt * 128;

    const int tid = threadIdx.x, lane = tid & 31, w = tid >> 5;
    const int g = lane >> 2, tg = lane & 3;
    const int j = lane & 7, mq = lane >> 3;
    const float SCL2E = 0.0450842144937583f;   // (1/32) * log2(e)

    const int lrow = j + ((mq & 1) << 3);
    const int lcol = (mq >> 1) << 3;
    const uint32_t aQ  = smu + (uint32_t)(((w * 16 + lrow) * QSH + lcol) * 2);
    const uint32_t kOf = (uint32_t)((lrow * KSH + lcol) * 2);
    const uint32_t kB0 = smu + Q_HL * 2 + kOf, kB1 = kB0 + K_HL * 2;
    const uint32_t vOf = (uint32_t)((lrow * VSH + lcol) * 2);
    const uint32_t vB0 = smu + (Q_HL + 2 * K_HL) * 2 + vOf, vB1 = vB0 + V_HL * 2;

    auto issue_kv = [&](int kt, int buf) {
#pragma unroll
        for (int u = 0; u < 4; u++) {
            const int i = tid + u * 256;
            const int r = i >> 4, ch = i & 15;
            cp16(Kb + buf * K_HL + r * KSH + ch * 8,
                 g_kh + ((size_t)(b * T_SEQ + kt * 64 + r)) * HSZ + ch * 8);
        }
#pragma unroll
        for (int u = 0; u < 4; u++) {
            const int i = tid + u * 256;
            const int r = i >> 3, ch = i & 7;
            cp16(Vb + buf * V_HL + r * VSH + ch * 8,
                 g_vth + ((size_t)(b * HSZ + r)) * T_SEQ + kt * 64 + ch * 8);
        }
    };

#pragma unroll
    for (int u = 0; u < 8; u++) {
        const int i = tid + u * 256;
        const int r = i >> 4, ch = i & 15;
        cp16(Qsh + r * QSH + ch * 8,
             g_qh + ((size_t)(b * T_SEQ + row0 + r)) * HSZ + ch * 8);
    }
    issue_kv(cs, 0); CP_COMMIT();
    if (cl > 1) issue_kv(cs + 1, 1);
    CP_COMMIT();

    float O[16][4];
#pragma unroll
    for (int no = 0; no < 16; no++)
#pragma unroll
        for (int q = 0; q < 4; q++) O[no][q] = 0.f;
    float lA = 0.f, lB = 0.f;

    const int rA = row0 + w * 16 + g;
    const int rB = rA + 8;

    for (int it = 0; it < cl; it++) {
        const int kt = cs + it;
        CP_WAIT1();
        __syncthreads();
        const uint32_t kB = (it & 1) ? kB1 : kB0;
        const uint32_t vB = (it & 1) ? vB1 : vB0;

        // ---- S = Q @ K^T : 16 x 64 per warp ----
        float s[8][4];
#pragma unroll
        for (int ni = 0; ni < 8; ni++)
#pragma unroll
            for (int q = 0; q < 4; q++) s[ni][q] = 0.f;

#pragma unroll
        for (int kf = 0; kf < 8; kf++) {
            unsigned a0, a1, a2, a3;
            ldsm4(a0, a1, a2, a3, aQ + kf * 32);
#pragma unroll
            for (int p = 0; p < 4; p++) {
                unsigned r0, r1, r2, r3;
                ldsm4(r0, r1, r2, r3,
                      kB + (uint32_t)(p * 16 * KSH * 2 + kf * 32));
                mma_f16(s[2*p][0], s[2*p][1], s[2*p][2], s[2*p][3],
                        a0, a1, a2, a3, r0, r2);
                mma_f16(s[2*p+1][0], s[2*p+1][1], s[2*p+1][2], s[2*p+1][3],
                        a0, a1, a2, a3, r1, r3);
            }
        }

        // ---- fused per-16-key chunks: exp + mask + pack + PV mma ----
        // (exp of chunk kf+1 overlaps PV HMMAs of chunk kf)
        const bool diag = (kt >= 2 * qt);
        const int relA = rA - kt * 64;   // valid cols: c <= relA
        const int relB = rB - kt * 64;
#pragma unroll
        for (int kf = 0; kf < 4; kf++) {
            float p[2][4];
#pragma unroll
            for (int h = 0; h < 2; h++) {
                const int ni = 2 * kf + h;
                const int c0 = ni * 8 + 2 * tg;
                float p0 = ex2f(s[ni][0] * SCL2E);
                float p1 = ex2f(s[ni][1] * SCL2E);
                float p2 = ex2f(s[ni][2] * SCL2E);
                float p3 = ex2f(s[ni][3] * SCL2E);
                if (diag) {
                    if (c0     > relA) p0 = 0.f;
                    if (c0 + 1 > relA) p1 = 0.f;
                    if (c0     > relB) p2 = 0.f;
                    if (c0 + 1 > relB) p3 = 0.f;
                }
                lA += p0 + p1; lB += p2 + p3;
                p[h][0] = p0; p[h][1] = p1; p[h][2] = p2; p[h][3] = p3;
            }
            const unsigned a0 = h2u(p[0][0], p[0][1]);
            const unsigned a1 = h2u(p[0][2], p[0][3]);
            const unsigned a2 = h2u(p[1][0], p[1][1]);
            const unsigned a3 = h2u(p[1][2], p[1][3]);
#pragma unroll
            for (int t = 0; t < 8; t++) {
                unsigned r0, r1, r2, r3;
                ldsm4(r0, r1, r2, r3,
                      vB + (uint32_t)(t * 16 * VSH * 2 + kf * 32));
                mma_f16(O[2*t][0], O[2*t][1], O[2*t][2], O[2*t][3],
                        a0, a1, a2, a3, r0, r2);
                mma_f16(O[2*t+1][0], O[2*t+1][1], O[2*t+1][2], O[2*t+1][3],
                        a0, a1, a2, a3, r1, r3);
            }
        }

        __syncthreads();
        if (it + 2 < cl) issue_kv(kt + 2, it & 1);
        CP_COMMIT();
    }

    lA += __shfl_xor_sync(0xffffffffu, lA, 1);
    lA += __shfl_xor_sync(0xffffffffu, lA, 2);
    lB += __shfl_xor_sync(0xffffffffu, lB, 1);
    lB += __shfl_xor_sync(0xffffffffu, lB, 2);

    float* op = g_opart + ((size_t)((b * 32 + qt) * 4 + sidx)) * (128 * 128);
    float* lp = g_lpart + ((size_t)((b * 32 + qt) * 4 + sidx)) * 128;
    const int rlA = w * 16 + g, rlB = rlA + 8;
    if (tg == 0) { lp[rlA] = lA; lp[rlB] = lB; }
#pragma unroll
    for (int no = 0; no < 16; no++) {
        const int c = no * 8 + 2 * tg;
        *reinterpret_cast<float2*>(op + (size_t)rlA * 128 + c) = make_float2(O[no][0], O[no][1]);
        *reinterpret_cast<float2*>(op + (size_t)rlB * 128 + c) = make_float2(O[no][2], O[no][3]);
    }
}

// ---------------------------------------------------------------------------
// Merge (proven at 8.4us)
// ---------------------------------------------------------------------------
__global__ __launch_bounds__(256) void merge_kernel(float* __restrict__ out)
{
    const int qt = blockIdx.x, rq = blockIdx.y, b = blockIdx.z;
    const int n = 2 * qt + 2, ns = (n + CH - 1) / CH;
    const int tid = threadIdx.x;
    const int r0 = rq * 32;

    __shared__ float linv[32];
    if (tid < 32) {
        float s = 0.f;
        const float* lp = g_lpart + ((size_t)((b * 32 + qt) * 4)) * 128 + r0 + tid;
#pragma unroll
        for (int sp = 0; sp < 4; sp++)
            if (sp < ns) s += lp[(size_t)sp * 128];
        linv[tid] = 1.f / s;
    }
    __syncthreads();

    const float* opb = g_opart + ((size_t)((b * 32 + qt) * 4)) * (128 * 128);
    float* dst = out + ((size_t)(b * T_SEQ + qt * 128 + r0)) * HSZ;

#pragma unroll
    for (int u = 0; u < 4; u++) {
        const int idx = tid + u * 256;
        const int row = idx >> 5, c4 = (idx & 31) * 4;
        float4 acc = make_float4(0.f, 0.f, 0.f, 0.f);
#pragma unroll
        for (int sp = 0; sp < 4; sp++) {
            if (sp < ns) {
                float4 v = *reinterpret_cast<const float4*>(
                    opb + (size_t)sp * 128 * 128 + (size_t)(r0 + row) * 128 + c4);
                acc.x += v.x; acc.y += v.y; acc.z += v.z; acc.w += v.w;
            }
        }
        const float li = linv[row];
        *reinterpret_cast<float4*>(dst + (size_t)row * 128 + c4) =
            make_float4(acc.x * li, acc.y * li, acc.z * li, acc.w * li);
    }
}

// ---------------------------------------------------------------------------
extern "C" void kernel_launch(void* const* d_in, const int* in_sizes, int n_in,
                              void* d_out, int out_size)
{
    const float* x  = (const float*)d_in[0];
    const float* Wq = (const float*)d_in[1];
    const float* Wk = (const float*)d_in[2];
    const float* Wv = (const float*)d_in[3];
    float* out = (float*)d_out;

    static bool attr_set = false;
    if (!attr_set) {
        cudaFuncSetAttribute(proj_kernel,
                             cudaFuncAttributeMaxDynamicSharedMemorySize, PROJ_SMEM);
        cudaFuncSetAttribute(attn_kernel,
                             cudaFuncAttributeMaxDynamicSharedMemorySize, ATTN_SMEM);
        attr_set = true;
    }

    xh_kernel<<<B_BATCH * T_SEQ * C_DIM / (256 * 8), 256>>>(x);
    wt_kernel<<<dim3(C_DIM / 32, HSZ / 32, 3), 256>>>(Wq, Wk, Wv);
    proj_kernel<<<dim3(128, 3), 256, PROJ_SMEM>>>();
    attn_kernel<<<dim3(74, B_BATCH), 256, ATTN_SMEM>>>();
    merge_kernel<<<dim3(32, 4, B_BATCH), 256>>>(out);
}